// round 14
// baseline (speedup 1.0000x reference)
#include <cuda_runtime.h>
#include <cuda_bf16.h>
#include <math.h>
#include <stdint.h>

// Problem constants
#define BATCH 2
#define CH    256
#define SEQ   2744      // 14*14*14
#define HEADS 4
#define DK    64
#define QKVD  768
#define FD    256       // HEADS * DK

// Scratch globals
__device__ __nv_bfloat16 g_q[(size_t)BATCH * HEADS * SEQ * DK];   // pre-scaled by SCL2
__device__ __nv_bfloat16 g_k[(size_t)BATCH * HEADS * SEQ * DK];
__device__ __nv_bfloat16 g_v[(size_t)BATCH * HEADS * SEQ * DK];
__device__ __nv_bfloat16 g_xb[(size_t)BATCH * CH * SEQ];    // x in bf16
__device__ __nv_bfloat16 g_wpb[(size_t)CH * QKVD];          // w_proj bf16
__device__ __nv_bfloat16 g_wob[(size_t)FD * CH];            // w_out bf16
// split-K attention partials: bf16 unnormalized O, fp32 row sums
__device__ __nv_bfloat16 g_ofb[2][(size_t)BATCH * SEQ * FD];
__device__ float g_lf[2][(size_t)BATCH * HEADS * SEQ];

// ---------------------------------------------------------------------------
// helpers
// ---------------------------------------------------------------------------
__device__ __forceinline__ uint32_t smem_to_u32(const void* p) {
    uint32_t a;
    asm("{ .reg .u64 t; cvta.to.shared.u64 t, %1; cvt.u32.u64 %0, t; }" : "=r"(a) : "l"(p));
    return a;
}
__device__ __forceinline__ void ldmx4(uint32_t& r0, uint32_t& r1, uint32_t& r2, uint32_t& r3,
                                      uint32_t addr) {
    asm volatile("ldmatrix.sync.aligned.m8n8.x4.shared.b16 {%0,%1,%2,%3}, [%4];"
                 : "=r"(r0), "=r"(r1), "=r"(r2), "=r"(r3) : "r"(addr));
}
__device__ __forceinline__ void ldmx4t(uint32_t& r0, uint32_t& r1, uint32_t& r2, uint32_t& r3,
                                       uint32_t addr) {
    asm volatile("ldmatrix.sync.aligned.m8n8.x4.trans.shared.b16 {%0,%1,%2,%3}, [%4];"
                 : "=r"(r0), "=r"(r1), "=r"(r2), "=r"(r3) : "r"(addr));
}
__device__ __forceinline__ void mma16816(float* c, const uint32_t* a, uint32_t b0, uint32_t b1) {
    asm volatile("mma.sync.aligned.m16n8k16.row.col.f32.bf16.bf16.f32 "
                 "{%0,%1,%2,%3}, {%4,%5,%6,%7}, {%8,%9}, {%0,%1,%2,%3};"
                 : "+f"(c[0]), "+f"(c[1]), "+f"(c[2]), "+f"(c[3])
                 : "r"(a[0]), "r"(a[1]), "r"(a[2]), "r"(a[3]), "r"(b0), "r"(b1));
}
__device__ __forceinline__ float ex2f(float x) {
    float r;
    asm("ex2.approx.ftz.f32 %0, %1;" : "=f"(r) : "f"(x));
    return r;
}
__device__ __forceinline__ uint32_t pack_bf2(float lo, float hi) {
    uint32_t d;
    asm("cvt.rn.bf16x2.f32 %0, %1, %2;" : "=r"(d) : "f"(hi), "f"(lo));
    return d;
}
__device__ __forceinline__ void cpa16(uint32_t dst, const void* src, int sz) {
    asm volatile("cp.async.cg.shared.global [%0], [%1], 16, %2;"
                 :: "r"(dst), "l"(src), "r"(sz) : "memory");
}
#define CP_COMMIT() asm volatile("cp.async.commit_group;" ::: "memory")
#define CP_WAIT(N)  asm volatile("cp.async.wait_group %0;" :: "n"(N) : "memory")

// XOR swizzles: rows of 128B (8 chunks) or 256B (16 chunks), 16B grain
#define SWZ(row, c16)    ((uint32_t)(row) * 128u + ((uint32_t)((c16) ^ ((row) & 7)) << 4))
#define SWZ256(row, c16) ((uint32_t)(row) * 256u + ((uint32_t)((c16) ^ ((row) & 7)) << 4))

// ---------------------------------------------------------------------------
// Kernel 0: fp32 -> bf16 conversion of x, w_proj, w_out
// ---------------------------------------------------------------------------
#define NX4  ((size_t)BATCH * CH * SEQ / 4)
#define NWP4 ((size_t)CH * QKVD / 4)
#define NWO4 ((size_t)FD * CH / 4)
#define NCVT4 (NX4 + NWP4 + NWO4)

__global__ void __launch_bounds__(256) cvt_kernel(const float* __restrict__ x,
                                                  const float* __restrict__ wp,
                                                  const float* __restrict__ wo) {
    size_t i4 = (size_t)blockIdx.x * 256 + threadIdx.x;
    const float* src;
    __nv_bfloat16* dst;
    size_t off;
    if (i4 < NX4)            { src = x;  dst = g_xb;  off = i4; }
    else if (i4 < NX4 + NWP4){ src = wp; dst = g_wpb; off = i4 - NX4; }
    else if (i4 < NCVT4)     { src = wo; dst = g_wob; off = i4 - NX4 - NWP4; }
    else return;
    float4 v = ((const float4*)src)[off];
    uint2 p = make_uint2(pack_bf2(v.x, v.y), pack_bf2(v.z, v.w));
    *(uint2*)(dst + off * 4) = p;
}

// ---------------------------------------------------------------------------
// Kernel 1: QKV projection, 128-thread CTAs (M=64), occupancy 4.
// m = s(64), n = out(128), k = c(256, 8 steps of 32). Q output pre-scaled.
// ---------------------------------------------------------------------------
#define SCL2 0.1803368801111244f  /* 0.125 * log2(e) */

__global__ void __launch_bounds__(128, 4) qkv_gemm(const float* __restrict__ bias) {
    __shared__ __align__(128) uint8_t sX[2][32 * 128];   // x [k32][s64]
    __shared__ __align__(128) uint8_t sW[2][32 * 256];   // w [k32][n128]

    const int t = threadIdx.x;
    const int wid = t >> 5;
    const int lane = t & 31;
    const int b = blockIdx.z;
    const int s0 = blockIdx.x * 64;
    const int n0 = blockIdx.y * 128;
    const uint32_t sX32 = smem_to_u32(sX);
    const uint32_t sW32 = smem_to_u32(sW);

    auto stage = [&](int ks, int buf) {
        const int k0 = ks * 32;
#pragma unroll
        for (int i = 0; i < 2; i++) {
            int idx = t + i * 128;
            int kk = idx >> 3, c16 = idx & 7;
            int s = s0 + c16 * 8;
            int sz = (s + 8 <= SEQ) ? 16 : 0;
            cpa16(sX32 + buf * 4096 + SWZ(kk, c16),
                  g_xb + ((size_t)b * CH + k0 + kk) * SEQ + s, sz);
        }
#pragma unroll
        for (int i = 0; i < 4; i++) {
            int idx = t + i * 128;
            int kk = idx >> 4, c16 = idx & 15;
            cpa16(sW32 + buf * 8192 + SWZ256(kk, c16),
                  g_wpb + (size_t)(k0 + kk) * QKVD + n0 + c16 * 8, 16);
        }
    };

    float c[16][4];
#pragma unroll
    for (int i = 0; i < 16; i++)
#pragma unroll
        for (int j = 0; j < 4; j++) c[i][j] = 0.f;

    stage(0, 0);
    CP_COMMIT();

#pragma unroll 1
    for (int ks = 0; ks < 8; ks++) {
        CP_WAIT(0);
        __syncthreads();
        if (ks + 1 < 8) { stage(ks + 1, (ks + 1) & 1); CP_COMMIT(); }
        const uint32_t bx = sX32 + (ks & 1) * 4096;
        const uint32_t bw = sW32 + (ks & 1) * 8192;

        uint32_t a[2][4];
#pragma unroll
        for (int kt = 0; kt < 2; kt++) {
            int row = kt * 16 + (lane & 7) + ((lane >> 4) << 3);
            int ch  = wid * 2 + ((lane >> 3) & 1);
            ldmx4t(a[kt][0], a[kt][1], a[kt][2], a[kt][3], bx + SWZ(row, ch));
        }
#pragma unroll
        for (int np = 0; np < 8; np++) {
#pragma unroll
            for (int kt = 0; kt < 2; kt++) {
                uint32_t b0, b1, b2, b3;
                int row = kt * 16 + (lane & 7) + (((lane >> 3) & 1) << 3);
                int ch  = np * 2 + (lane >> 4);
                ldmx4t(b0, b1, b2, b3, bw + SWZ256(row, ch));
                mma16816(c[np * 2],     a[kt], b0, b1);
                mma16816(c[np * 2 + 1], a[kt], b2, b3);
            }
        }
    }

    const int sq0 = s0 + wid * 16 + (lane >> 2);
    const int sq1 = sq0 + 8;
#pragma unroll
    for (int nt = 0; nt < 16; nt++) {
        int n = n0 + nt * 8 + (lane & 3) * 2;
        int h = n / 192;
        int r = n - h * 192;
        int kind = r >> 6;
        int d = r & 63;
        __nv_bfloat16* arr = (kind == 0) ? g_q : (kind == 1) ? g_k : g_v;
        const float scl = (kind == 0) ? SCL2 : 1.f;   // pre-scale Q
        float2 bb = *(const float2*)&bias[n];
        size_t base = (size_t)(b * HEADS + h) * SEQ;
        if (sq0 < SEQ)
            *(__nv_bfloat162*)(arr + (base + sq0) * 64 + d) =
                __floats2bfloat162_rn((c[nt][0] + bb.x) * scl, (c[nt][1] + bb.y) * scl);
        if (sq1 < SEQ)
            *(__nv_bfloat162*)(arr + (base + sq1) * 64 + d) =
                __floats2bfloat162_rn((c[nt][2] + bb.x) * scl, (c[nt][3] + bb.y) * scl);
    }
}

// ---------------------------------------------------------------------------
// Kernel 2: FA2-style bf16 flash attention, 2-way split-K, bf16 partials.
// blockIdx.z = b*2 + half; half 0: key blocks 0..21, half 1: 22..42.
// ---------------------------------------------------------------------------
#define NBLK 43

__global__ void __launch_bounds__(128, 4) attn_kernel() {
    __shared__ __align__(128) uint8_t sQ[64 * 128];
    __shared__ __align__(128) uint8_t sK[2][64 * 128];
    __shared__ __align__(128) uint8_t sV[2][64 * 128];

    const int t = threadIdx.x;
    const int wid = t >> 5;
    const int lane = t & 31;
    const int b = blockIdx.z >> 1;
    const int kh = blockIdx.z & 1;
    const int h = blockIdx.y;
    const int q0 = blockIdx.x * 64;
    const int ib0 = kh * 22;
    const int ib1 = kh ? NBLK : 22;
    const size_t bh = (size_t)(b * HEADS + h) * SEQ;
    const uint32_t sQ32 = smem_to_u32(sQ);
    const uint32_t sK32 = smem_to_u32(sK);
    const uint32_t sV32 = smem_to_u32(sV);

    auto stage_kv = [&](int ib, int buf) {
        const int jb = ib * 64;
        const uint32_t bo = buf * 8192;
#pragma unroll
        for (int i = 0; i < 4; i++) {
            int idx = t + i * 128;               // 0..511
            int row = idx >> 3, c16 = idx & 7;
            int s = jb + row;
            int sz = (s < SEQ) ? 16 : 0;
            uint32_t off = bo + SWZ(row, c16);
            cpa16(sK32 + off, g_k + (bh + s) * 64 + c16 * 8, sz);
            cpa16(sV32 + off, g_v + (bh + s) * 64 + c16 * 8, sz);
        }
    };

    // Q staging
#pragma unroll
    for (int i = 0; i < 4; i++) {
        int idx = t + i * 128;
        int row = idx >> 3, c16 = idx & 7;
        int s = q0 + row;
        cpa16(sQ32 + SWZ(row, c16), g_q + (bh + s) * 64 + c16 * 8, (s < SEQ) ? 16 : 0);
    }
    stage_kv(ib0, ib0 & 1);
    CP_COMMIT();
    CP_WAIT(0);
    __syncthreads();

    const int m0 = wid * 16;
    uint32_t aQ[4][4];
#pragma unroll
    for (int kt = 0; kt < 4; kt++) {
        int row = m0 + (lane & 15);
        int c16 = kt * 2 + (lane >> 4);
        ldmx4(aQ[kt][0], aQ[kt][1], aQ[kt][2], aQ[kt][3], sQ32 + SWZ(row, c16));
    }

    float o[8][4];
#pragma unroll
    for (int i = 0; i < 8; i++)
#pragma unroll
        for (int j = 0; j < 4; j++) o[i][j] = 0.f;
    float lsum0 = 0.f, lsum1 = 0.f;

#pragma unroll 1
    for (int ib = ib0; ib < ib1; ib++) {
        if (ib > ib0) {
            CP_WAIT(0);
            __syncthreads();
        }
        if (ib + 1 < ib1) { stage_kv(ib + 1, (ib + 1) & 1); CP_COMMIT(); }

        const uint32_t bK = sK32 + (ib & 1) * 8192;
        const uint32_t bV = sV32 + (ib & 1) * 8192;

        float c[8][4];
#pragma unroll
        for (int i = 0; i < 8; i++)
#pragma unroll
            for (int j = 0; j < 4; j++) c[i][j] = 0.f;

#pragma unroll
        for (int nt = 0; nt < 8; nt++) {
#pragma unroll
            for (int p = 0; p < 2; p++) {
                uint32_t b0, b1, b2, b3;
                int row = nt * 8 + (lane & 7);
                int c16 = 4 * p + (lane >> 3);
                ldmx4(b0, b1, b2, b3, bK + SWZ(row, c16));
                mma16816(c[nt], aQ[2 * p],     b0, b1);
                mma16816(c[nt], aQ[2 * p + 1], b2, b3);
            }
        }

        uint32_t pa[4][4];
        const bool domask = (ib == NBLK - 1);
#pragma unroll
        for (int nt = 0; nt < 8; nt++) {
            float e0 = ex2f(c[nt][0]);
            float e1 = ex2f(c[nt][1]);
            float e2 = ex2f(c[nt][2]);
            float e3 = ex2f(c[nt][3]);
            if (domask) {
                int j = (NBLK - 1) * 64 + nt * 8 + (lane & 3) * 2;
                if (j     >= SEQ) { e0 = 0.f; e2 = 0.f; }
                if (j + 1 >= SEQ) { e1 = 0.f; e3 = 0.f; }
            }
            lsum0 += e0 + e1;
            lsum1 += e2 + e3;
            int kt = nt >> 1;
            int hi = (nt & 1) ? 2 : 0;
            pa[kt][hi]     = pack_bf2(e0, e1);
            pa[kt][hi + 1] = pack_bf2(e2, e3);
        }

#pragma unroll
        for (int kt = 0; kt < 4; kt++) {
#pragma unroll
            for (int np = 0; np < 4; np++) {
                uint32_t b0, b1, b2, b3;
                int row = kt * 16 + (lane & 7) + (((lane >> 3) & 1) << 3);
                int c16 = np * 2 + (lane >> 4);
                ldmx4t(b0, b1, b2, b3, bV + SWZ(row, c16));
                mma16816(o[np * 2],     pa[kt], b0, b1);
                mma16816(o[np * 2 + 1], pa[kt], b2, b3);
            }
        }
    }

    lsum0 += __shfl_xor_sync(0xFFFFFFFFu, lsum0, 1);
    lsum0 += __shfl_xor_sync(0xFFFFFFFFu, lsum0, 2);
    lsum1 += __shfl_xor_sync(0xFFFFFFFFu, lsum1, 1);
    lsum1 += __shfl_xor_sync(0xFFFFFFFFu, lsum1, 2);

    const int r0 = q0 + m0 + (lane >> 2);
    const int r1 = r0 + 8;
    const int colb = h * 64 + (lane & 3) * 2;
    __nv_bfloat16* obase = g_ofb[kh];
    float* lbase = g_lf[kh];
    if (r0 < SEQ) {
        __nv_bfloat16* dst = obase + ((size_t)b * SEQ + r0) * FD + colb;
#pragma unroll
        for (int nt = 0; nt < 8; nt++)
            *(uint32_t*)(dst + nt * 8) = pack_bf2(o[nt][0], o[nt][1]);
        if ((lane & 3) == 0) lbase[(bh + r0)] = lsum0;
    }
    if (r1 < SEQ) {
        __nv_bfloat16* dst = obase + ((size_t)b * SEQ + r1) * FD + colb;
#pragma unroll
        for (int nt = 0; nt < 8; nt++)
            *(uint32_t*)(dst + nt * 8) = pack_bf2(o[nt][2], o[nt][3]);
        if ((lane & 3) == 0) lbase[(bh + r1)] = lsum1;
    }
}

// ---------------------------------------------------------------------------
// Kernel 3: output projection, FUSED split-K combine + bias + residual.
// m = c(64), n = s(64), k = f(256, 4 steps of 64; head h = ks).
// Stages BOTH bf16 partial buffers; combines in B-fragment registers:
// frag = (pa + pb) * inv_l[s].  inv uniform per lane per nt (n = lane>>2).
// smem: 3 x 2 x 8KB = 48KB. Grid 43x4x2 = 344 CTAs.
// ---------------------------------------------------------------------------
__global__ void __launch_bounds__(128, 4) out_gemm(const float* __restrict__ x,
                                                  const float* __restrict__ bias,
                                                  float* __restrict__ out) {
    __shared__ __align__(128) uint8_t sPa[2][64 * 128];  // O half 0 [s64][f64]
    __shared__ __align__(128) uint8_t sPb[2][64 * 128];  // O half 1 [s64][f64]
    __shared__ __align__(128) uint8_t sW[2][64 * 128];   // w_out [f64][c64]

    const int t = threadIdx.x;
    const int wid = t >> 5;
    const int lane = t & 31;
    const int b = blockIdx.z;
    const int s0 = blockIdx.x * 64;
    const int c0 = blockIdx.y * 64;
    const uint32_t sPa32 = smem_to_u32(sPa);
    const uint32_t sPb32 = smem_to_u32(sPb);
    const uint32_t sW32 = smem_to_u32(sW);

    auto stage = [&](int ks, int buf) {
        const int f0 = ks * 64;
#pragma unroll
        for (int i = 0; i < 4; i++) {
            int idx = t + i * 128;               // 0..511
            int row = idx >> 3, c16 = idx & 7;
            int s = s0 + row;
            int sz = (s < SEQ) ? 16 : 0;
            size_t goff = ((size_t)b * SEQ + s) * FD + f0 + c16 * 8;
            uint32_t so = buf * 8192 + SWZ(row, c16);
            cpa16(sPa32 + so, g_ofb[0] + goff, sz);
            cpa16(sPb32 + so, g_ofb[1] + goff, sz);
            cpa16(sW32 + so, g_wob + (size_t)(f0 + row) * FD + c0 + c16 * 8, 16);
        }
    };

    float c[8][4];
#pragma unroll
    for (int i = 0; i < 8; i++)
#pragma unroll
        for (int j = 0; j < 4; j++) c[i][j] = 0.f;

    stage(0, 0);
    CP_COMMIT();

#pragma unroll 1
    for (int ks = 0; ks < 4; ks++) {
        CP_WAIT(0);
        __syncthreads();
        if (ks + 1 < 4) { stage(ks + 1, (ks + 1) & 1); CP_COMMIT(); }
        const uint32_t bPa = sPa32 + (ks & 1) * 8192;
        const uint32_t bPb = sPb32 + (ks & 1) * 8192;
        const uint32_t bW  = sW32  + (ks & 1) * 8192;

        // per-lane inverse row sums for this head (h = ks); n = lane>>2
        const float* l0 = g_lf[0] + ((size_t)b * HEADS + ks) * SEQ;
        const float* l1 = g_lf[1] + ((size_t)b * HEADS + ks) * SEQ;
        float invv[8];
#pragma unroll
        for (int nt = 0; nt < 8; nt++) {
            int s = s0 + nt * 8 + (lane >> 2);
            invv[nt] = (s < SEQ) ? __frcp_rn(__ldg(l0 + s) + __ldg(l1 + s)) : 0.f;
        }

        uint32_t a[4][4];
#pragma unroll
        for (int kt = 0; kt < 4; kt++) {
            int row = kt * 16 + (lane & 7) + ((lane >> 4) << 3);
            int ch  = wid * 2 + ((lane >> 3) & 1);
            ldmx4t(a[kt][0], a[kt][1], a[kt][2], a[kt][3], bW + SWZ(row, ch));
        }
#pragma unroll
        for (int nt = 0; nt < 8; nt++) {
            const __nv_bfloat162 iv2 = __float2bfloat162_rn(invv[nt]);
#pragma unroll
            for (int p = 0; p < 2; p++) {
                uint32_t a0, a1, a2, a3, d0, d1, d2, d3;
                int row = nt * 8 + (lane & 7);
                int c16 = p * 4 + (lane >> 3);
                uint32_t off = SWZ(row, c16);
                ldmx4(a0, a1, a2, a3, bPa + off);
                ldmx4(d0, d1, d2, d3, bPb + off);
                uint32_t b0, b1, b2, b3;
                {
                    __nv_bfloat162 r;
                    r = __hmul2(__hadd2(*(__nv_bfloat162*)&a0, *(__nv_bfloat162*)&d0), iv2);
                    b0 = *(uint32_t*)&r;
                    r = __hmul2(__hadd2(*(__nv_bfloat162*)&a1, *(__nv_bfloat162*)&d1), iv2);
                    b1 = *(uint32_t*)&r;
                    r = __hmul2(__hadd2(*(__nv_bfloat162*)&a2, *(__nv_bfloat162*)&d2), iv2);
                    b2 = *(uint32_t*)&r;
                    r = __hmul2(__hadd2(*(__nv_bfloat162*)&a3, *(__nv_bfloat162*)&d3), iv2);
                    b3 = *(uint32_t*)&r;
                }
                mma16816(c[nt], a[2 * p],     b0, b1);
                mma16816(c[nt], a[2 * p + 1], b2, b3);
            }
        }
    }

    const int cc0 = c0 + wid * 16 + (lane >> 2);
    const int cc1 = cc0 + 8;
    const float bb0 = bias[cc0];
    const float bb1 = bias[cc1];
#pragma unroll
    for (int nt = 0; nt < 8; nt++) {
        int s = s0 + nt * 8 + (lane & 3) * 2;
        if (s < SEQ) {
            size_t g0 = ((size_t)b * CH + cc0) * SEQ + s;
            size_t g1 = ((size_t)b * CH + cc1) * SEQ + s;
            float2 x0 = *(const float2*)&x[g0];
            float2 x1 = *(const float2*)&x[g1];
            *(float2*)&out[g0] = make_float2(c[nt][0] + bb0 + x0.x, c[nt][1] + bb0 + x0.y);
            *(float2*)&out[g1] = make_float2(c[nt][2] + bb1 + x1.x, c[nt][3] + bb1 + x1.y);
        }
    }
}

// ---------------------------------------------------------------------------
extern "C" void kernel_launch(void* const* d_in, const int* in_sizes, int n_in,
                              void* d_out, int out_size) {
    const float* x      = (const float*)d_in[0];
    const float* w_proj = (const float*)d_in[1];
    const float* b_proj = (const float*)d_in[2];
    const float* w_out  = (const float*)d_in[3];
    const float* b_out  = (const float*)d_in[4];
    float* out = (float*)d_out;

    cvt_kernel<<<1628, 256>>>(x, w_proj, w_out);
    qkv_gemm<<<dim3(43, 6, BATCH), 128>>>(b_proj);
    attn_kernel<<<dim3(43, HEADS, BATCH * 2), 128>>>();
    out_gemm<<<dim3(43, 4, BATCH), 128>>>(x, b_out, out);
}

// round 15
// speedup vs baseline: 1.1012x; 1.1012x over previous
#include <cuda_runtime.h>
#include <cuda_bf16.h>
#include <math.h>
#include <stdint.h>

// Problem constants
#define BATCH 2
#define CH    256
#define SEQ   2744      // 14*14*14
#define HEADS 4
#define DK    64
#define QKVD  768
#define FD    256       // HEADS * DK

// Scratch globals
__device__ __nv_bfloat16 g_q[(size_t)BATCH * HEADS * SEQ * DK];   // pre-scaled by SCL2
__device__ __nv_bfloat16 g_k[(size_t)BATCH * HEADS * SEQ * DK];
__device__ __nv_bfloat16 g_v[(size_t)BATCH * HEADS * SEQ * DK];
__device__ __nv_bfloat16 g_att[(size_t)BATCH * SEQ * FD];   // [b][s][h*64+d]
__device__ __nv_bfloat16 g_xb[(size_t)BATCH * CH * SEQ];    // x in bf16
__device__ __nv_bfloat16 g_wpb[(size_t)CH * QKVD];          // w_proj bf16
__device__ __nv_bfloat16 g_wob[(size_t)FD * CH];            // w_out bf16
// split-K attention partials: bf16 unnormalized O, fp32 row sums
__device__ __nv_bfloat16 g_ofb[2][(size_t)BATCH * SEQ * FD];
__device__ float g_lf[2][(size_t)BATCH * HEADS * SEQ];

// ---------------------------------------------------------------------------
// helpers
// ---------------------------------------------------------------------------
__device__ __forceinline__ uint32_t smem_to_u32(const void* p) {
    uint32_t a;
    asm("{ .reg .u64 t; cvta.to.shared.u64 t, %1; cvt.u32.u64 %0, t; }" : "=r"(a) : "l"(p));
    return a;
}
__device__ __forceinline__ void ldmx4(uint32_t& r0, uint32_t& r1, uint32_t& r2, uint32_t& r3,
                                      uint32_t addr) {
    asm volatile("ldmatrix.sync.aligned.m8n8.x4.shared.b16 {%0,%1,%2,%3}, [%4];"
                 : "=r"(r0), "=r"(r1), "=r"(r2), "=r"(r3) : "r"(addr));
}
__device__ __forceinline__ void ldmx4t(uint32_t& r0, uint32_t& r1, uint32_t& r2, uint32_t& r3,
                                       uint32_t addr) {
    asm volatile("ldmatrix.sync.aligned.m8n8.x4.trans.shared.b16 {%0,%1,%2,%3}, [%4];"
                 : "=r"(r0), "=r"(r1), "=r"(r2), "=r"(r3) : "r"(addr));
}
__device__ __forceinline__ void mma16816(float* c, const uint32_t* a, uint32_t b0, uint32_t b1) {
    asm volatile("mma.sync.aligned.m16n8k16.row.col.f32.bf16.bf16.f32 "
                 "{%0,%1,%2,%3}, {%4,%5,%6,%7}, {%8,%9}, {%0,%1,%2,%3};"
                 : "+f"(c[0]), "+f"(c[1]), "+f"(c[2]), "+f"(c[3])
                 : "r"(a[0]), "r"(a[1]), "r"(a[2]), "r"(a[3]), "r"(b0), "r"(b1));
}
__device__ __forceinline__ float ex2f(float x) {
    float r;
    asm("ex2.approx.ftz.f32 %0, %1;" : "=f"(r) : "f"(x));
    return r;
}
__device__ __forceinline__ uint32_t pack_bf2(float lo, float hi) {
    uint32_t d;
    asm("cvt.rn.bf16x2.f32 %0, %1, %2;" : "=r"(d) : "f"(hi), "f"(lo));
    return d;
}
__device__ __forceinline__ void cpa16(uint32_t dst, const void* src, int sz) {
    asm volatile("cp.async.cg.shared.global [%0], [%1], 16, %2;"
                 :: "r"(dst), "l"(src), "r"(sz) : "memory");
}
#define CP_COMMIT() asm volatile("cp.async.commit_group;" ::: "memory")
#define CP_WAIT(N)  asm volatile("cp.async.wait_group %0;" :: "n"(N) : "memory")

// XOR swizzles: rows of 128B (8 chunks) or 256B (16 chunks), 16B grain
#define SWZ(row, c16)    ((uint32_t)(row) * 128u + ((uint32_t)((c16) ^ ((row) & 7)) << 4))
#define SWZ256(row, c16) ((uint32_t)(row) * 256u + ((uint32_t)((c16) ^ ((row) & 7)) << 4))

// ---------------------------------------------------------------------------
// Kernel 0: fp32 -> bf16 conversion of x, w_proj, w_out
// ---------------------------------------------------------------------------
#define NX4  ((size_t)BATCH * CH * SEQ / 4)
#define NWP4 ((size_t)CH * QKVD / 4)
#define NWO4 ((size_t)FD * CH / 4)
#define NCVT4 (NX4 + NWP4 + NWO4)

__global__ void __launch_bounds__(256) cvt_kernel(const float* __restrict__ x,
                                                  const float* __restrict__ wp,
                                                  const float* __restrict__ wo) {
    size_t i4 = (size_t)blockIdx.x * 256 + threadIdx.x;
    const float* src;
    __nv_bfloat16* dst;
    size_t off;
    if (i4 < NX4)            { src = x;  dst = g_xb;  off = i4; }
    else if (i4 < NX4 + NWP4){ src = wp; dst = g_wpb; off = i4 - NX4; }
    else if (i4 < NCVT4)     { src = wo; dst = g_wob; off = i4 - NX4 - NWP4; }
    else return;
    float4 v = ((const float4*)src)[off];
    uint2 p = make_uint2(pack_bf2(v.x, v.y), pack_bf2(v.z, v.w));
    *(uint2*)(dst + off * 4) = p;
}

// ---------------------------------------------------------------------------
// Kernel 1: QKV projection, 128-thread CTAs (M=64), occupancy 4.
// m = s(64), n = out(128), k = c(256, 8 steps of 32). Q output pre-scaled.
// ---------------------------------------------------------------------------
#define SCL2 0.1803368801111244f  /* 0.125 * log2(e) */

__global__ void __launch_bounds__(128, 4) qkv_gemm(const float* __restrict__ bias) {
    __shared__ __align__(128) uint8_t sX[2][32 * 128];   // x [k32][s64]
    __shared__ __align__(128) uint8_t sW[2][32 * 256];   // w [k32][n128]

    const int t = threadIdx.x;
    const int wid = t >> 5;
    const int lane = t & 31;
    const int b = blockIdx.z;
    const int s0 = blockIdx.x * 64;
    const int n0 = blockIdx.y * 128;
    const uint32_t sX32 = smem_to_u32(sX);
    const uint32_t sW32 = smem_to_u32(sW);

    auto stage = [&](int ks, int buf) {
        const int k0 = ks * 32;
#pragma unroll
        for (int i = 0; i < 2; i++) {
            int idx = t + i * 128;
            int kk = idx >> 3, c16 = idx & 7;
            int s = s0 + c16 * 8;
            int sz = (s + 8 <= SEQ) ? 16 : 0;
            cpa16(sX32 + buf * 4096 + SWZ(kk, c16),
                  g_xb + ((size_t)b * CH + k0 + kk) * SEQ + s, sz);
        }
#pragma unroll
        for (int i = 0; i < 4; i++) {
            int idx = t + i * 128;
            int kk = idx >> 4, c16 = idx & 15;
            cpa16(sW32 + buf * 8192 + SWZ256(kk, c16),
                  g_wpb + (size_t)(k0 + kk) * QKVD + n0 + c16 * 8, 16);
        }
    };

    float c[16][4];
#pragma unroll
    for (int i = 0; i < 16; i++)
#pragma unroll
        for (int j = 0; j < 4; j++) c[i][j] = 0.f;

    stage(0, 0);
    CP_COMMIT();

#pragma unroll 1
    for (int ks = 0; ks < 8; ks++) {
        CP_WAIT(0);
        __syncthreads();
        if (ks + 1 < 8) { stage(ks + 1, (ks + 1) & 1); CP_COMMIT(); }
        const uint32_t bx = sX32 + (ks & 1) * 4096;
        const uint32_t bw = sW32 + (ks & 1) * 8192;

        uint32_t a[2][4];
#pragma unroll
        for (int kt = 0; kt < 2; kt++) {
            int row = kt * 16 + (lane & 7) + ((lane >> 4) << 3);
            int ch  = wid * 2 + ((lane >> 3) & 1);
            ldmx4t(a[kt][0], a[kt][1], a[kt][2], a[kt][3], bx + SWZ(row, ch));
        }
#pragma unroll
        for (int np = 0; np < 8; np++) {
#pragma unroll
            for (int kt = 0; kt < 2; kt++) {
                uint32_t b0, b1, b2, b3;
                int row = kt * 16 + (lane & 7) + (((lane >> 3) & 1) << 3);
                int ch  = np * 2 + (lane >> 4);
                ldmx4t(b0, b1, b2, b3, bw + SWZ256(row, ch));
                mma16816(c[np * 2],     a[kt], b0, b1);
                mma16816(c[np * 2 + 1], a[kt], b2, b3);
            }
        }
    }

    const int sq0 = s0 + wid * 16 + (lane >> 2);
    const int sq1 = sq0 + 8;
#pragma unroll
    for (int nt = 0; nt < 16; nt++) {
        int n = n0 + nt * 8 + (lane & 3) * 2;
        int h = n / 192;
        int r = n - h * 192;
        int kind = r >> 6;
        int d = r & 63;
        __nv_bfloat16* arr = (kind == 0) ? g_q : (kind == 1) ? g_k : g_v;
        const float scl = (kind == 0) ? SCL2 : 1.f;   // pre-scale Q
        float2 bb = *(const float2*)&bias[n];
        size_t base = (size_t)(b * HEADS + h) * SEQ;
        if (sq0 < SEQ)
            *(__nv_bfloat162*)(arr + (base + sq0) * 64 + d) =
                __floats2bfloat162_rn((c[nt][0] + bb.x) * scl, (c[nt][1] + bb.y) * scl);
        if (sq1 < SEQ)
            *(__nv_bfloat162*)(arr + (base + sq1) * 64 + d) =
                __floats2bfloat162_rn((c[nt][2] + bb.x) * scl, (c[nt][3] + bb.y) * scl);
    }
}

// ---------------------------------------------------------------------------
// Kernel 2: FA2-style bf16 flash attention, 2-way split-K, bf16 partials.
// blockIdx.z = b*2 + half; half 0: key blocks 0..21, half 1: 22..42.
// ---------------------------------------------------------------------------
#define NBLK 43

__global__ void __launch_bounds__(128, 4) attn_kernel() {
    __shared__ __align__(128) uint8_t sQ[64 * 128];
    __shared__ __align__(128) uint8_t sK[2][64 * 128];
    __shared__ __align__(128) uint8_t sV[2][64 * 128];

    const int t = threadIdx.x;
    const int wid = t >> 5;
    const int lane = t & 31;
    const int b = blockIdx.z >> 1;
    const int kh = blockIdx.z & 1;
    const int h = blockIdx.y;
    const int q0 = blockIdx.x * 64;
    const int ib0 = kh * 22;
    const int ib1 = kh ? NBLK : 22;
    const size_t bh = (size_t)(b * HEADS + h) * SEQ;
    const uint32_t sQ32 = smem_to_u32(sQ);
    const uint32_t sK32 = smem_to_u32(sK);
    const uint32_t sV32 = smem_to_u32(sV);

    auto stage_kv = [&](int ib, int buf) {
        const int jb = ib * 64;
        const uint32_t bo = buf * 8192;
#pragma unroll
        for (int i = 0; i < 4; i++) {
            int idx = t + i * 128;               // 0..511
            int row = idx >> 3, c16 = idx & 7;
            int s = jb + row;
            int sz = (s < SEQ) ? 16 : 0;
            uint32_t off = bo + SWZ(row, c16);
            cpa16(sK32 + off, g_k + (bh + s) * 64 + c16 * 8, sz);
            cpa16(sV32 + off, g_v + (bh + s) * 64 + c16 * 8, sz);
        }
    };

    // Q staging
#pragma unroll
    for (int i = 0; i < 4; i++) {
        int idx = t + i * 128;
        int row = idx >> 3, c16 = idx & 7;
        int s = q0 + row;
        cpa16(sQ32 + SWZ(row, c16), g_q + (bh + s) * 64 + c16 * 8, (s < SEQ) ? 16 : 0);
    }
    stage_kv(ib0, ib0 & 1);
    CP_COMMIT();
    CP_WAIT(0);
    __syncthreads();

    const int m0 = wid * 16;
    uint32_t aQ[4][4];
#pragma unroll
    for (int kt = 0; kt < 4; kt++) {
        int row = m0 + (lane & 15);
        int c16 = kt * 2 + (lane >> 4);
        ldmx4(aQ[kt][0], aQ[kt][1], aQ[kt][2], aQ[kt][3], sQ32 + SWZ(row, c16));
    }

    float o[8][4];
#pragma unroll
    for (int i = 0; i < 8; i++)
#pragma unroll
        for (int j = 0; j < 4; j++) o[i][j] = 0.f;
    float lsum0 = 0.f, lsum1 = 0.f;

#pragma unroll 1
    for (int ib = ib0; ib < ib1; ib++) {
        if (ib > ib0) {
            CP_WAIT(0);
            __syncthreads();
        }
        if (ib + 1 < ib1) { stage_kv(ib + 1, (ib + 1) & 1); CP_COMMIT(); }

        const uint32_t bK = sK32 + (ib & 1) * 8192;
        const uint32_t bV = sV32 + (ib & 1) * 8192;

        float c[8][4];
#pragma unroll
        for (int i = 0; i < 8; i++)
#pragma unroll
            for (int j = 0; j < 4; j++) c[i][j] = 0.f;

#pragma unroll
        for (int nt = 0; nt < 8; nt++) {
#pragma unroll
            for (int p = 0; p < 2; p++) {
                uint32_t b0, b1, b2, b3;
                int row = nt * 8 + (lane & 7);
                int c16 = 4 * p + (lane >> 3);
                ldmx4(b0, b1, b2, b3, bK + SWZ(row, c16));
                mma16816(c[nt], aQ[2 * p],     b0, b1);
                mma16816(c[nt], aQ[2 * p + 1], b2, b3);
            }
        }

        uint32_t pa[4][4];
        const bool domask = (ib == NBLK - 1);
#pragma unroll
        for (int nt = 0; nt < 8; nt++) {
            float e0 = ex2f(c[nt][0]);
            float e1 = ex2f(c[nt][1]);
            float e2 = ex2f(c[nt][2]);
            float e3 = ex2f(c[nt][3]);
            if (domask) {
                int j = (NBLK - 1) * 64 + nt * 8 + (lane & 3) * 2;
                if (j     >= SEQ) { e0 = 0.f; e2 = 0.f; }
                if (j + 1 >= SEQ) { e1 = 0.f; e3 = 0.f; }
            }
            lsum0 += e0 + e1;
            lsum1 += e2 + e3;
            int kt = nt >> 1;
            int hi = (nt & 1) ? 2 : 0;
            pa[kt][hi]     = pack_bf2(e0, e1);
            pa[kt][hi + 1] = pack_bf2(e2, e3);
        }

#pragma unroll
        for (int kt = 0; kt < 4; kt++) {
#pragma unroll
            for (int np = 0; np < 4; np++) {
                uint32_t b0, b1, b2, b3;
                int row = kt * 16 + (lane & 7) + (((lane >> 3) & 1) << 3);
                int c16 = np * 2 + (lane >> 4);
                ldmx4t(b0, b1, b2, b3, bV + SWZ(row, c16));
                mma16816(o[np * 2],     pa[kt], b0, b1);
                mma16816(o[np * 2 + 1], pa[kt], b2, b3);
            }
        }
    }

    lsum0 += __shfl_xor_sync(0xFFFFFFFFu, lsum0, 1);
    lsum0 += __shfl_xor_sync(0xFFFFFFFFu, lsum0, 2);
    lsum1 += __shfl_xor_sync(0xFFFFFFFFu, lsum1, 1);
    lsum1 += __shfl_xor_sync(0xFFFFFFFFu, lsum1, 2);

    const int r0 = q0 + m0 + (lane >> 2);
    const int r1 = r0 + 8;
    const int colb = h * 64 + (lane & 3) * 2;
    __nv_bfloat16* obase = g_ofb[kh];
    float* lbase = g_lf[kh];
    if (r0 < SEQ) {
        __nv_bfloat16* dst = obase + ((size_t)b * SEQ + r0) * FD + colb;
#pragma unroll
        for (int nt = 0; nt < 8; nt++)
            *(uint32_t*)(dst + nt * 8) = pack_bf2(o[nt][0], o[nt][1]);
        if ((lane & 3) == 0) lbase[(bh + r0)] = lsum0;
    }
    if (r1 < SEQ) {
        __nv_bfloat16* dst = obase + ((size_t)b * SEQ + r1) * FD + colb;
#pragma unroll
        for (int nt = 0; nt < 8; nt++)
            *(uint32_t*)(dst + nt * 8) = pack_bf2(o[nt][2], o[nt][3]);
        if ((lane & 3) == 0) lbase[(bh + r1)] = lsum1;
    }
}

// ---------------------------------------------------------------------------
// Kernel 2b: combine bf16 split-K halves, normalize, emit bf16 g_att.
// 16 elements per thread (two uint4 per half); one l lookup per thread
// (each 16-elem chunk lies within a single head).
// ---------------------------------------------------------------------------
#define NCOMB16 ((size_t)BATCH * SEQ * FD / 16)   // 87808 -> 343 CTAs * 256

__global__ void __launch_bounds__(256) combine_kernel() {
    size_t i16 = (size_t)blockIdx.x * 256 + threadIdx.x;
    if (i16 >= NCOMB16) return;
    size_t rem = i16 % ((size_t)SEQ * FD / 16);
    int b = (int)(i16 / ((size_t)SEQ * FD / 16));
    int s = (int)(rem / (FD / 16));
    int f16i = (int)(rem % (FD / 16));
    int h = (f16i * 16) >> 6;

    float l = g_lf[0][((size_t)b * HEADS + h) * SEQ + s] +
              g_lf[1][((size_t)b * HEADS + h) * SEQ + s];
    float inv = 1.f / l;

    const uint4* p0 = (const uint4*)g_ofb[0] + i16 * 2;
    const uint4* p1 = (const uint4*)g_ofb[1] + i16 * 2;
    uint4* dst = (uint4*)g_att + i16 * 2;
#pragma unroll
    for (int q = 0; q < 2; q++) {
        uint4 a = p0[q];
        uint4 c = p1[q];
        uint32_t r[4];
        const uint32_t* av = &a.x;
        const uint32_t* cv = &c.x;
#pragma unroll
        for (int i = 0; i < 4; i++) {
            __nv_bfloat162 x0 = *(const __nv_bfloat162*)&av[i];
            __nv_bfloat162 x1 = *(const __nv_bfloat162*)&cv[i];
            r[i] = pack_bf2((__bfloat162float(x0.x) + __bfloat162float(x1.x)) * inv,
                            (__bfloat162float(x0.y) + __bfloat162float(x1.y)) * inv);
        }
        dst[q] = make_uint4(r[0], r[1], r[2], r[3]);
    }
}

// ---------------------------------------------------------------------------
// Kernel 3: output projection + bias + residual, 3-stage pipeline.
// m = c(64), n = s(64), k = f(256, 4 steps of 64). Grid 43x4x2 = 344 CTAs.
// ---------------------------------------------------------------------------
__global__ void __launch_bounds__(128, 4) out_gemm(const float* __restrict__ x,
                                                  const float* __restrict__ bias,
                                                  float* __restrict__ out) {
    __shared__ __align__(128) uint8_t sP[3][64 * 128];  // att [s64][f64]
    __shared__ __align__(128) uint8_t sW[3][64 * 128];  // w_out [f64][c64]

    const int t = threadIdx.x;
    const int wid = t >> 5;
    const int lane = t & 31;
    const int b = blockIdx.z;
    const int s0 = blockIdx.x * 64;
    const int c0 = blockIdx.y * 64;
    const uint32_t sP32 = smem_to_u32(sP);
    const uint32_t sW32 = smem_to_u32(sW);

    auto stage = [&](int ks, int buf) {
        const int f0 = ks * 64;
#pragma unroll
        for (int i = 0; i < 4; i++) {
            int idx = t + i * 128;               // 0..511
            int row = idx >> 3, c16 = idx & 7;
            {
                int s = s0 + row;
                cpa16(sP32 + buf * 8192 + SWZ(row, c16),
                      g_att + ((size_t)b * SEQ + s) * FD + f0 + c16 * 8,
                      (s < SEQ) ? 16 : 0);
            }
            cpa16(sW32 + buf * 8192 + SWZ(row, c16),
                  g_wob + (size_t)(f0 + row) * FD + c0 + c16 * 8, 16);
        }
    };

    float c[8][4];
#pragma unroll
    for (int i = 0; i < 8; i++)
#pragma unroll
        for (int j = 0; j < 4; j++) c[i][j] = 0.f;

    stage(0, 0); CP_COMMIT();
    stage(1, 1); CP_COMMIT();

#pragma unroll 1
    for (int ks = 0; ks < 4; ks++) {
        if (ks < 3) CP_WAIT(1); else CP_WAIT(0);
        __syncthreads();
        if (ks + 2 < 4) { stage(ks + 2, (ks + 2) % 3); CP_COMMIT(); }
        const uint32_t bP = sP32 + (ks % 3) * 8192;
        const uint32_t bW = sW32 + (ks % 3) * 8192;

        uint32_t a[4][4];
#pragma unroll
        for (int kt = 0; kt < 4; kt++) {
            int row = kt * 16 + (lane & 7) + ((lane >> 4) << 3);
            int ch  = wid * 2 + ((lane >> 3) & 1);
            ldmx4t(a[kt][0], a[kt][1], a[kt][2], a[kt][3], bW + SWZ(row, ch));
        }
#pragma unroll
        for (int nt = 0; nt < 8; nt++) {
#pragma unroll
            for (int p = 0; p < 2; p++) {
                uint32_t b0, b1, b2, b3;
                int row = nt * 8 + (lane & 7);
                int c16 = p * 4 + (lane >> 3);
                ldmx4(b0, b1, b2, b3, bP + SWZ(row, c16));
                mma16816(c[nt], a[2 * p],     b0, b1);
                mma16816(c[nt], a[2 * p + 1], b2, b3);
            }
        }
    }

    const int cc0 = c0 + wid * 16 + (lane >> 2);
    const int cc1 = cc0 + 8;
    const float bb0 = bias[cc0];
    const float bb1 = bias[cc1];
#pragma unroll
    for (int nt = 0; nt < 8; nt++) {
        int s = s0 + nt * 8 + (lane & 3) * 2;
        if (s < SEQ) {
            size_t g0 = ((size_t)b * CH + cc0) * SEQ + s;
            size_t g1 = ((size_t)b * CH + cc1) * SEQ + s;
            float2 x0 = *(const float2*)&x[g0];
            float2 x1 = *(const float2*)&x[g1];
            *(float2*)&out[g0] = make_float2(c[nt][0] + bb0 + x0.x, c[nt][1] + bb0 + x0.y);
            *(float2*)&out[g1] = make_float2(c[nt][2] + bb1 + x1.x, c[nt][3] + bb1 + x1.y);
        }
    }
}

// ---------------------------------------------------------------------------
extern "C" void kernel_launch(void* const* d_in, const int* in_sizes, int n_in,
                              void* d_out, int out_size) {
    const float* x      = (const float*)d_in[0];
    const float* w_proj = (const float*)d_in[1];
    const float* b_proj = (const float*)d_in[2];
    const float* w_out  = (const float*)d_in[3];
    const float* b_out  = (const float*)d_in[4];
    float* out = (float*)d_out;

    cvt_kernel<<<1628, 256>>>(x, w_proj, w_out);
    qkv_gemm<<<dim3(43, 6, BATCH), 128>>>(b_proj);
    attn_kernel<<<dim3(43, HEADS, BATCH * 2), 128>>>();
    combine_kernel<<<343, 256>>>();
    out_gemm<<<dim3(43, 4, BATCH), 128>>>(x, b_out, out);
}

// round 16
// speedup vs baseline: 1.1170x; 1.0144x over previous
#include <cuda_runtime.h>
#include <cuda_bf16.h>
#include <math.h>
#include <stdint.h>

// Problem constants
#define BATCH 2
#define CH    256
#define SEQ   2744      // 14*14*14
#define HEADS 4
#define DK    64
#define QKVD  768
#define FD    256       // HEADS * DK

// Scratch globals
__device__ __nv_bfloat16 g_q[(size_t)BATCH * HEADS * SEQ * DK];   // pre-scaled by SCL2
__device__ __nv_bfloat16 g_k[(size_t)BATCH * HEADS * SEQ * DK];
__device__ __nv_bfloat16 g_v[(size_t)BATCH * HEADS * SEQ * DK];
__device__ __nv_bfloat16 g_att[(size_t)BATCH * SEQ * FD];   // [b][s][h*64+d]
__device__ __nv_bfloat16 g_xb[(size_t)BATCH * CH * SEQ];    // x in bf16
__device__ __nv_bfloat16 g_wpb[(size_t)CH * QKVD];          // w_proj bf16
__device__ __nv_bfloat16 g_wob[(size_t)FD * CH];            // w_out bf16
// split-K attention partials: bf16 unnormalized O, fp32 row sums
__device__ __nv_bfloat16 g_ofb[2][(size_t)BATCH * SEQ * FD];
__device__ float g_lf[2][(size_t)BATCH * HEADS * SEQ];

// ---------------------------------------------------------------------------
// helpers
// ---------------------------------------------------------------------------
__device__ __forceinline__ uint32_t smem_to_u32(const void* p) {
    uint32_t a;
    asm("{ .reg .u64 t; cvta.to.shared.u64 t, %1; cvt.u32.u64 %0, t; }" : "=r"(a) : "l"(p));
    return a;
}
__device__ __forceinline__ void ldmx4(uint32_t& r0, uint32_t& r1, uint32_t& r2, uint32_t& r3,
                                      uint32_t addr) {
    asm volatile("ldmatrix.sync.aligned.m8n8.x4.shared.b16 {%0,%1,%2,%3}, [%4];"
                 : "=r"(r0), "=r"(r1), "=r"(r2), "=r"(r3) : "r"(addr));
}
__device__ __forceinline__ void ldmx4t(uint32_t& r0, uint32_t& r1, uint32_t& r2, uint32_t& r3,
                                       uint32_t addr) {
    asm volatile("ldmatrix.sync.aligned.m8n8.x4.trans.shared.b16 {%0,%1,%2,%3}, [%4];"
                 : "=r"(r0), "=r"(r1), "=r"(r2), "=r"(r3) : "r"(addr));
}
__device__ __forceinline__ void mma16816(float* c, const uint32_t* a, uint32_t b0, uint32_t b1) {
    asm volatile("mma.sync.aligned.m16n8k16.row.col.f32.bf16.bf16.f32 "
                 "{%0,%1,%2,%3}, {%4,%5,%6,%7}, {%8,%9}, {%0,%1,%2,%3};"
                 : "+f"(c[0]), "+f"(c[1]), "+f"(c[2]), "+f"(c[3])
                 : "r"(a[0]), "r"(a[1]), "r"(a[2]), "r"(a[3]), "r"(b0), "r"(b1));
}
__device__ __forceinline__ float ex2f(float x) {
    float r;
    asm("ex2.approx.ftz.f32 %0, %1;" : "=f"(r) : "f"(x));
    return r;
}
__device__ __forceinline__ uint32_t pack_bf2(float lo, float hi) {
    uint32_t d;
    asm("cvt.rn.bf16x2.f32 %0, %1, %2;" : "=r"(d) : "f"(hi), "f"(lo));
    return d;
}
__device__ __forceinline__ void cpa16(uint32_t dst, const void* src, int sz) {
    asm volatile("cp.async.cg.shared.global [%0], [%1], 16, %2;"
                 :: "r"(dst), "l"(src), "r"(sz) : "memory");
}
#define CP_COMMIT() asm volatile("cp.async.commit_group;" ::: "memory")
#define CP_WAIT(N)  asm volatile("cp.async.wait_group %0;" :: "n"(N) : "memory")

// XOR swizzles: rows of 128B (8 chunks) or 256B (16 chunks), 16B grain
#define SWZ(row, c16)    ((uint32_t)(row) * 128u + ((uint32_t)((c16) ^ ((row) & 7)) << 4))
#define SWZ256(row, c16) ((uint32_t)(row) * 256u + ((uint32_t)((c16) ^ ((row) & 7)) << 4))

// ---------------------------------------------------------------------------
// Kernel 0: fp32 -> bf16 conversion of x, w_proj, w_out
// ---------------------------------------------------------------------------
#define NX4  ((size_t)BATCH * CH * SEQ / 4)
#define NWP4 ((size_t)CH * QKVD / 4)
#define NWO4 ((size_t)FD * CH / 4)
#define NCVT4 (NX4 + NWP4 + NWO4)

__global__ void __launch_bounds__(256) cvt_kernel(const float* __restrict__ x,
                                                  const float* __restrict__ wp,
                                                  const float* __restrict__ wo) {
    size_t i4 = (size_t)blockIdx.x * 256 + threadIdx.x;
    const float* src;
    __nv_bfloat16* dst;
    size_t off;
    if (i4 < NX4)            { src = x;  dst = g_xb;  off = i4; }
    else if (i4 < NX4 + NWP4){ src = wp; dst = g_wpb; off = i4 - NX4; }
    else if (i4 < NCVT4)     { src = wo; dst = g_wob; off = i4 - NX4 - NWP4; }
    else return;
    float4 v = ((const float4*)src)[off];
    uint2 p = make_uint2(pack_bf2(v.x, v.y), pack_bf2(v.z, v.w));
    *(uint2*)(dst + off * 4) = p;
}

// ---------------------------------------------------------------------------
// Kernel 1: QKV projection, 128-thread CTAs (M=64), occupancy 4.
// m = s(64), n = out(128), k = c(256, 8 steps of 32). Q output pre-scaled.
// ---------------------------------------------------------------------------
#define SCL2 0.1803368801111244f  /* 0.125 * log2(e) */

__global__ void __launch_bounds__(128, 4) qkv_gemm(const float* __restrict__ bias) {
    __shared__ __align__(128) uint8_t sX[2][32 * 128];   // x [k32][s64]
    __shared__ __align__(128) uint8_t sW[2][32 * 256];   // w [k32][n128]

    const int t = threadIdx.x;
    const int wid = t >> 5;
    const int lane = t & 31;
    const int b = blockIdx.z;
    const int s0 = blockIdx.x * 64;
    const int n0 = blockIdx.y * 128;
    const uint32_t sX32 = smem_to_u32(sX);
    const uint32_t sW32 = smem_to_u32(sW);

    auto stage = [&](int ks, int buf) {
        const int k0 = ks * 32;
#pragma unroll
        for (int i = 0; i < 2; i++) {
            int idx = t + i * 128;
            int kk = idx >> 3, c16 = idx & 7;
            int s = s0 + c16 * 8;
            int sz = (s + 8 <= SEQ) ? 16 : 0;
            cpa16(sX32 + buf * 4096 + SWZ(kk, c16),
                  g_xb + ((size_t)b * CH + k0 + kk) * SEQ + s, sz);
        }
#pragma unroll
        for (int i = 0; i < 4; i++) {
            int idx = t + i * 128;
            int kk = idx >> 4, c16 = idx & 15;
            cpa16(sW32 + buf * 8192 + SWZ256(kk, c16),
                  g_wpb + (size_t)(k0 + kk) * QKVD + n0 + c16 * 8, 16);
        }
    };

    float c[16][4];
#pragma unroll
    for (int i = 0; i < 16; i++)
#pragma unroll
        for (int j = 0; j < 4; j++) c[i][j] = 0.f;

    stage(0, 0);
    CP_COMMIT();

#pragma unroll 1
    for (int ks = 0; ks < 8; ks++) {
        CP_WAIT(0);
        __syncthreads();
        if (ks + 1 < 8) { stage(ks + 1, (ks + 1) & 1); CP_COMMIT(); }
        const uint32_t bx = sX32 + (ks & 1) * 4096;
        const uint32_t bw = sW32 + (ks & 1) * 8192;

        uint32_t a[2][4];
#pragma unroll
        for (int kt = 0; kt < 2; kt++) {
            int row = kt * 16 + (lane & 7) + ((lane >> 4) << 3);
            int ch  = wid * 2 + ((lane >> 3) & 1);
            ldmx4t(a[kt][0], a[kt][1], a[kt][2], a[kt][3], bx + SWZ(row, ch));
        }
#pragma unroll
        for (int np = 0; np < 8; np++) {
#pragma unroll
            for (int kt = 0; kt < 2; kt++) {
                uint32_t b0, b1, b2, b3;
                int row = kt * 16 + (lane & 7) + (((lane >> 3) & 1) << 3);
                int ch  = np * 2 + (lane >> 4);
                ldmx4t(b0, b1, b2, b3, bw + SWZ256(row, ch));
                mma16816(c[np * 2],     a[kt], b0, b1);
                mma16816(c[np * 2 + 1], a[kt], b2, b3);
            }
        }
    }

    const int sq0 = s0 + wid * 16 + (lane >> 2);
    const int sq1 = sq0 + 8;
#pragma unroll
    for (int nt = 0; nt < 16; nt++) {
        int n = n0 + nt * 8 + (lane & 3) * 2;
        int h = n / 192;
        int r = n - h * 192;
        int kind = r >> 6;
        int d = r & 63;
        __nv_bfloat16* arr = (kind == 0) ? g_q : (kind == 1) ? g_k : g_v;
        const float scl = (kind == 0) ? SCL2 : 1.f;   // pre-scale Q
        float2 bb = *(const float2*)&bias[n];
        size_t base = (size_t)(b * HEADS + h) * SEQ;
        if (sq0 < SEQ)
            *(__nv_bfloat162*)(arr + (base + sq0) * 64 + d) =
                __floats2bfloat162_rn((c[nt][0] + bb.x) * scl, (c[nt][1] + bb.y) * scl);
        if (sq1 < SEQ)
            *(__nv_bfloat162*)(arr + (base + sq1) * 64 + d) =
                __floats2bfloat162_rn((c[nt][2] + bb.x) * scl, (c[nt][3] + bb.y) * scl);
    }
}

// ---------------------------------------------------------------------------
// Kernel 2: FA2-style bf16 flash attention, 2-way split-K, bf16 partials.
// blockIdx.z = b*2 + half; half 0: key blocks 0..21, half 1: 22..42.
// ---------------------------------------------------------------------------
#define NBLK 43

__global__ void __launch_bounds__(128, 4) attn_kernel() {
    __shared__ __align__(128) uint8_t sQ[64 * 128];
    __shared__ __align__(128) uint8_t sK[2][64 * 128];
    __shared__ __align__(128) uint8_t sV[2][64 * 128];

    const int t = threadIdx.x;
    const int wid = t >> 5;
    const int lane = t & 31;
    const int b = blockIdx.z >> 1;
    const int kh = blockIdx.z & 1;
    const int h = blockIdx.y;
    const int q0 = blockIdx.x * 64;
    const int ib0 = kh * 22;
    const int ib1 = kh ? NBLK : 22;
    const size_t bh = (size_t)(b * HEADS + h) * SEQ;
    const uint32_t sQ32 = smem_to_u32(sQ);
    const uint32_t sK32 = smem_to_u32(sK);
    const uint32_t sV32 = smem_to_u32(sV);

    auto stage_kv = [&](int ib, int buf) {
        const int jb = ib * 64;
        const uint32_t bo = buf * 8192;
#pragma unroll
        for (int i = 0; i < 4; i++) {
            int idx = t + i * 128;               // 0..511
            int row = idx >> 3, c16 = idx & 7;
            int s = jb + row;
            int sz = (s < SEQ) ? 16 : 0;
            uint32_t off = bo + SWZ(row, c16);
            cpa16(sK32 + off, g_k + (bh + s) * 64 + c16 * 8, sz);
            cpa16(sV32 + off, g_v + (bh + s) * 64 + c16 * 8, sz);
        }
    };

    // Q staging
#pragma unroll
    for (int i = 0; i < 4; i++) {
        int idx = t + i * 128;
        int row = idx >> 3, c16 = idx & 7;
        int s = q0 + row;
        cpa16(sQ32 + SWZ(row, c16), g_q + (bh + s) * 64 + c16 * 8, (s < SEQ) ? 16 : 0);
    }
    stage_kv(ib0, ib0 & 1);
    CP_COMMIT();
    CP_WAIT(0);
    __syncthreads();

    const int m0 = wid * 16;
    uint32_t aQ[4][4];
#pragma unroll
    for (int kt = 0; kt < 4; kt++) {
        int row = m0 + (lane & 15);
        int c16 = kt * 2 + (lane >> 4);
        ldmx4(aQ[kt][0], aQ[kt][1], aQ[kt][2], aQ[kt][3], sQ32 + SWZ(row, c16));
    }

    float o[8][4];
#pragma unroll
    for (int i = 0; i < 8; i++)
#pragma unroll
        for (int j = 0; j < 4; j++) o[i][j] = 0.f;
    float lsum0 = 0.f, lsum1 = 0.f;

#pragma unroll 1
    for (int ib = ib0; ib < ib1; ib++) {
        if (ib > ib0) {
            CP_WAIT(0);
            __syncthreads();
        }
        if (ib + 1 < ib1) { stage_kv(ib + 1, (ib + 1) & 1); CP_COMMIT(); }

        const uint32_t bK = sK32 + (ib & 1) * 8192;
        const uint32_t bV = sV32 + (ib & 1) * 8192;

        float c[8][4];
#pragma unroll
        for (int i = 0; i < 8; i++)
#pragma unroll
            for (int j = 0; j < 4; j++) c[i][j] = 0.f;

#pragma unroll
        for (int nt = 0; nt < 8; nt++) {
#pragma unroll
            for (int p = 0; p < 2; p++) {
                uint32_t b0, b1, b2, b3;
                int row = nt * 8 + (lane & 7);
                int c16 = 4 * p + (lane >> 3);
                ldmx4(b0, b1, b2, b3, bK + SWZ(row, c16));
                mma16816(c[nt], aQ[2 * p],     b0, b1);
                mma16816(c[nt], aQ[2 * p + 1], b2, b3);
            }
        }

        uint32_t pa[4][4];
        const bool domask = (ib == NBLK - 1);
#pragma unroll
        for (int nt = 0; nt < 8; nt++) {
            float e0 = ex2f(c[nt][0]);
            float e1 = ex2f(c[nt][1]);
            float e2 = ex2f(c[nt][2]);
            float e3 = ex2f(c[nt][3]);
            if (domask) {
                int j = (NBLK - 1) * 64 + nt * 8 + (lane & 3) * 2;
                if (j     >= SEQ) { e0 = 0.f; e2 = 0.f; }
                if (j + 1 >= SEQ) { e1 = 0.f; e3 = 0.f; }
            }
            lsum0 += e0 + e1;
            lsum1 += e2 + e3;
            int kt = nt >> 1;
            int hi = (nt & 1) ? 2 : 0;
            pa[kt][hi]     = pack_bf2(e0, e1);
            pa[kt][hi + 1] = pack_bf2(e2, e3);
        }

#pragma unroll
        for (int kt = 0; kt < 4; kt++) {
#pragma unroll
            for (int np = 0; np < 4; np++) {
                uint32_t b0, b1, b2, b3;
                int row = kt * 16 + (lane & 7) + (((lane >> 3) & 1) << 3);
                int c16 = np * 2 + (lane >> 4);
                ldmx4t(b0, b1, b2, b3, bV + SWZ(row, c16));
                mma16816(o[np * 2],     pa[kt], b0, b1);
                mma16816(o[np * 2 + 1], pa[kt], b2, b3);
            }
        }
    }

    lsum0 += __shfl_xor_sync(0xFFFFFFFFu, lsum0, 1);
    lsum0 += __shfl_xor_sync(0xFFFFFFFFu, lsum0, 2);
    lsum1 += __shfl_xor_sync(0xFFFFFFFFu, lsum1, 1);
    lsum1 += __shfl_xor_sync(0xFFFFFFFFu, lsum1, 2);

    const int r0 = q0 + m0 + (lane >> 2);
    const int r1 = r0 + 8;
    const int colb = h * 64 + (lane & 3) * 2;
    __nv_bfloat16* obase = g_ofb[kh];
    float* lbase = g_lf[kh];
    if (r0 < SEQ) {
        __nv_bfloat16* dst = obase + ((size_t)b * SEQ + r0) * FD + colb;
#pragma unroll
        for (int nt = 0; nt < 8; nt++)
            *(uint32_t*)(dst + nt * 8) = pack_bf2(o[nt][0], o[nt][1]);
        if ((lane & 3) == 0) lbase[(bh + r0)] = lsum0;
    }
    if (r1 < SEQ) {
        __nv_bfloat16* dst = obase + ((size_t)b * SEQ + r1) * FD + colb;
#pragma unroll
        for (int nt = 0; nt < 8; nt++)
            *(uint32_t*)(dst + nt * 8) = pack_bf2(o[nt][2], o[nt][3]);
        if ((lane & 3) == 0) lbase[(bh + r1)] = lsum1;
    }
}

// ---------------------------------------------------------------------------
// Kernel 2b: combine bf16 split-K halves, normalize, emit bf16 g_att.
// 4 elements per thread (uint2 per half) = maximum thread count for latency
// hiding (empirical: duration tracks occupancy inversely). 512-thr blocks.
// ---------------------------------------------------------------------------
#define NCOMB4C ((size_t)BATCH * SEQ * FD / 4)   // 351232 -> 686 CTAs * 512

__global__ void __launch_bounds__(512) combine_kernel() {
    size_t i4 = (size_t)blockIdx.x * 512 + threadIdx.x;
    if (i4 >= NCOMB4C) return;
    size_t rem = i4 % ((size_t)SEQ * FD / 4);
    int b = (int)(i4 / ((size_t)SEQ * FD / 4));
    int s = (int)(rem / (FD / 4));
    int f4 = (int)(rem % (FD / 4));
    int h = f4 >> 4;                      // (f4*4)>>6

    float l = __ldg(&g_lf[0][((size_t)b * HEADS + h) * SEQ + s]) +
              __ldg(&g_lf[1][((size_t)b * HEADS + h) * SEQ + s]);
    float inv = 1.f / l;

    uint2 a = *((const uint2*)g_ofb[0] + i4);
    uint2 c = *((const uint2*)g_ofb[1] + i4);
    uint32_t r[2];
    const uint32_t* av = &a.x;
    const uint32_t* cv = &c.x;
#pragma unroll
    for (int i = 0; i < 2; i++) {
        __nv_bfloat162 x0 = *(const __nv_bfloat162*)&av[i];
        __nv_bfloat162 x1 = *(const __nv_bfloat162*)&cv[i];
        r[i] = pack_bf2((__bfloat162float(x0.x) + __bfloat162float(x1.x)) * inv,
                        (__bfloat162float(x0.y) + __bfloat162float(x1.y)) * inv);
    }
    *((uint2*)g_att + i4) = make_uint2(r[0], r[1]);
}

// ---------------------------------------------------------------------------
// Kernel 3: output projection + bias + residual, 3-stage pipeline.
// m = c(64), n = s(64), k = f(256, 4 steps of 64). Grid 43x4x2 = 344 CTAs.
// ---------------------------------------------------------------------------
__global__ void __launch_bounds__(128, 4) out_gemm(const float* __restrict__ x,
                                                  const float* __restrict__ bias,
                                                  float* __restrict__ out) {
    __shared__ __align__(128) uint8_t sP[3][64 * 128];  // att [s64][f64]
    __shared__ __align__(128) uint8_t sW[3][64 * 128];  // w_out [f64][c64]

    const int t = threadIdx.x;
    const int wid = t >> 5;
    const int lane = t & 31;
    const int b = blockIdx.z;
    const int s0 = blockIdx.x * 64;
    const int c0 = blockIdx.y * 64;
    const uint32_t sP32 = smem_to_u32(sP);
    const uint32_t sW32 = smem_to_u32(sW);

    auto stage = [&](int ks, int buf) {
        const int f0 = ks * 64;
#pragma unroll
        for (int i = 0; i < 4; i++) {
            int idx = t + i * 128;               // 0..511
            int row = idx >> 3, c16 = idx & 7;
            {
                int s = s0 + row;
                cpa16(sP32 + buf * 8192 + SWZ(row, c16),
                      g_att + ((size_t)b * SEQ + s) * FD + f0 + c16 * 8,
                      (s < SEQ) ? 16 : 0);
            }
            cpa16(sW32 + buf * 8192 + SWZ(row, c16),
                  g_wob + (size_t)(f0 + row) * FD + c0 + c16 * 8, 16);
        }
    };

    float c[8][4];
#pragma unroll
    for (int i = 0; i < 8; i++)
#pragma unroll
        for (int j = 0; j < 4; j++) c[i][j] = 0.f;

    stage(0, 0); CP_COMMIT();
    stage(1, 1); CP_COMMIT();

#pragma unroll 1
    for (int ks = 0; ks < 4; ks++) {
        if (ks < 3) CP_WAIT(1); else CP_WAIT(0);
        __syncthreads();
        if (ks + 2 < 4) { stage(ks + 2, (ks + 2) % 3); CP_COMMIT(); }
        const uint32_t bP = sP32 + (ks % 3) * 8192;
        const uint32_t bW = sW32 + (ks % 3) * 8192;

        uint32_t a[4][4];
#pragma unroll
        for (int kt = 0; kt < 4; kt++) {
            int row = kt * 16 + (lane & 7) + ((lane >> 4) << 3);
            int ch  = wid * 2 + ((lane >> 3) & 1);
            ldmx4t(a[kt][0], a[kt][1], a[kt][2], a[kt][3], bW + SWZ(row, ch));
        }
#pragma unroll
        for (int nt = 0; nt < 8; nt++) {
#pragma unroll
            for (int p = 0; p < 2; p++) {
                uint32_t b0, b1, b2, b3;
                int row = nt * 8 + (lane & 7);
                int c16 = p * 4 + (lane >> 3);
                ldmx4(b0, b1, b2, b3, bP + SWZ(row, c16));
                mma16816(c[nt], a[2 * p],     b0, b1);
                mma16816(c[nt], a[2 * p + 1], b2, b3);
            }
        }
    }

    const int cc0 = c0 + wid * 16 + (lane >> 2);
    const int cc1 = cc0 + 8;
    const float bb0 = bias[cc0];
    const float bb1 = bias[cc1];
#pragma unroll
    for (int nt = 0; nt < 8; nt++) {
        int s = s0 + nt * 8 + (lane & 3) * 2;
        if (s < SEQ) {
            size_t g0 = ((size_t)b * CH + cc0) * SEQ + s;
            size_t g1 = ((size_t)b * CH + cc1) * SEQ + s;
            float2 x0 = *(const float2*)&x[g0];
            float2 x1 = *(const float2*)&x[g1];
            *(float2*)&out[g0] = make_float2(c[nt][0] + bb0 + x0.x, c[nt][1] + bb0 + x0.y);
            *(float2*)&out[g1] = make_float2(c[nt][2] + bb1 + x1.x, c[nt][3] + bb1 + x1.y);
        }
    }
}

// ---------------------------------------------------------------------------
extern "C" void kernel_launch(void* const* d_in, const int* in_sizes, int n_in,
                              void* d_out, int out_size) {
    const float* x      = (const float*)d_in[0];
    const float* w_proj = (const float*)d_in[1];
    const float* b_proj = (const float*)d_in[2];
    const float* w_out  = (const float*)d_in[3];
    const float* b_out  = (const float*)d_in[4];
    float* out = (float*)d_out;

    cvt_kernel<<<1628, 256>>>(x, w_proj, w_out);
    qkv_gemm<<<dim3(43, 6, BATCH), 128>>>(b_proj);
    attn_kernel<<<dim3(43, HEADS, BATCH * 2), 128>>>();
    combine_kernel<<<686, 512>>>();
    out_gemm<<<dim3(43, 4, BATCH), 128>>>(x, b_out, out);
}